// round 10
// baseline (speedup 1.0000x reference)
#include <cuda_runtime.h>
#include <cstdint>

// ---------------- constants ----------------
#define B_   8
#define CIN  64
#define COUT 64
#define H_   96
#define W_   96
#define HW   (H_*W_)          // 9216
#define KK   9                // 3x3 taps
#define OFFC 18               // 2*KK offset channels
#define PIT  132              // sS pixel pitch (16B-aligned rows)

// ---------------- f32x2 helpers (Blackwell packed fp32) ----------------
__device__ __forceinline__ unsigned long long fma2(unsigned long long a,
                                                   unsigned long long b,
                                                   unsigned long long c) {
    unsigned long long d;
    asm("fma.rn.f32x2 %0, %1, %2, %3;" : "=l"(d) : "l"(a), "l"(b), "l"(c));
    return d;
}
__device__ __forceinline__ unsigned long long pack2(float lo, float hi) {
    unsigned long long d;
    asm("mov.b64 %0, {%1, %2};" : "=l"(d) : "f"(lo), "f"(hi));
    return d;
}
__device__ __forceinline__ float2 unpack2(unsigned long long v) {
    float2 r;
    asm("mov.b64 {%0, %1}, %2;" : "=f"(r.x), "=f"(r.y) : "l"(v));
    return r;
}

// ---------------- scratch ----------------
__device__ float g_xT[B_ * HW * CIN];       // NHWC transposed x
__device__ float g_off[B_ * OFFC * HW];     // offset field
__device__ float g_wT[KK * CIN * COUT];     // weight as [kk][c][oc]

// ============================================================
// Kernel 1: NCHW -> NHWC transpose of x
// ============================================================
__global__ __launch_bounds__(256) void transpose_x_kernel(const float* __restrict__ x)
{
    __shared__ float tile[32][33];
    int b   = blockIdx.z;
    int hw0 = blockIdx.x * 32;
    int c0  = blockIdx.y * 32;
    int tx = threadIdx.x, ty = threadIdx.y;

    const float* src = x + (size_t)b * CIN * HW;
#pragma unroll
    for (int i = 0; i < 32; i += 8)
        tile[ty + i][tx] = src[(size_t)(c0 + ty + i) * HW + hw0 + tx];
    __syncthreads();
    float* dst = g_xT + (size_t)b * HW * CIN;
#pragma unroll
    for (int i = 0; i < 32; i += 8)
        dst[(size_t)(hw0 + ty + i) * CIN + c0 + tx] = tile[tx][ty + i];
}

// ============================================================
// Kernel 2: weight (oc, c, kk) -> wT[kk][c][oc]
// ============================================================
__global__ __launch_bounds__(256) void transpose_w_kernel(const float* __restrict__ w)
{
    int idx = blockIdx.x * 256 + threadIdx.x;
    if (idx < COUT * CIN * KK) {
        int kk = idx % KK;
        int c  = (idx / KK) % CIN;
        int oc = idx / (KK * CIN);
        g_wT[(kk * CIN + c) * COUT + oc] = w[idx];
    }
}

// ============================================================
// Kernel 3: offset conv with f32x2
// ============================================================
__global__ __launch_bounds__(256) void offset_conv_kernel(
    const float* __restrict__ x,
    const float* __restrict__ off_w,
    const float* __restrict__ off_b)
{
    __shared__ float wS[576][20];

    int tid = threadIdx.x;
    for (int i = tid; i < OFFC * 576; i += 256) {
        int o = i / 576;
        int r = i % 576;
        wS[r][o] = off_w[i];
    }
    for (int r = tid; r < 576; r += 256) { wS[r][18] = 0.f; wS[r][19] = 0.f; }
    __syncthreads();

    int b   = blockIdx.z;
    int wo  = blockIdx.x * 32 + (tid & 31);
    int ho  = blockIdx.y * 8  + (tid >> 5);

    unsigned long long acc2[9];
#pragma unroll
    for (int j = 0; j < 9; ++j) acc2[j] = 0ull;

    const float* xb = x + (size_t)b * CIN * HW;

    for (int c = 0; c < CIN; ++c) {
        const float* xc = xb + (size_t)c * HW;
#pragma unroll
        for (int kh = 0; kh < 3; ++kh) {
            int y = ho + kh - 1;
            bool vy = ((unsigned)y < (unsigned)H_);
#pragma unroll
            for (int kw = 0; kw < 3; ++kw) {
                int xx = wo + kw - 1;
                float xv = 0.f;
                if (vy && (unsigned)xx < (unsigned)W_)
                    xv = __ldg(xc + y * W_ + xx);
                unsigned long long xp = pack2(xv, xv);
                const float* wr = &wS[c * 9 + kh * 3 + kw][0];
                ulonglong2 wA = *(const ulonglong2*)(wr + 0);
                ulonglong2 wB = *(const ulonglong2*)(wr + 4);
                ulonglong2 wC = *(const ulonglong2*)(wr + 8);
                ulonglong2 wD = *(const ulonglong2*)(wr + 12);
                unsigned long long wE = *(const unsigned long long*)(wr + 16);
                acc2[0] = fma2(xp, wA.x, acc2[0]);
                acc2[1] = fma2(xp, wA.y, acc2[1]);
                acc2[2] = fma2(xp, wB.x, acc2[2]);
                acc2[3] = fma2(xp, wB.y, acc2[3]);
                acc2[4] = fma2(xp, wC.x, acc2[4]);
                acc2[5] = fma2(xp, wC.y, acc2[5]);
                acc2[6] = fma2(xp, wD.x, acc2[6]);
                acc2[7] = fma2(xp, wD.y, acc2[7]);
                acc2[8] = fma2(xp, wE,   acc2[8]);
            }
        }
    }

#pragma unroll
    for (int j = 0; j < 9; ++j) {
        float2 f = unpack2(acc2[j]);
        g_off[((size_t)(b * OFFC + 2 * j)     * H_ + ho) * W_ + wo] = f.x + __ldg(&off_b[2 * j]);
        g_off[((size_t)(b * OFFC + 2 * j + 1) * H_ + ho) * W_ + wo] = f.y + __ldg(&off_b[2 * j + 1]);
    }
}

// ============================================================
// Kernel 4: deformable conv main — wavefront-minimized v2
// block: 128 pixels (8 ho x 16 wo) x 64 oc, 256 threads, grid (6,12,8)=576
// smem (dynamic 50.2KB): sS[64][PIT] + wSh[64][64]   -> 4 CTAs/SM
// warp w owns output row ho0+w, 16 wo pixels, processed as 4 quads:
//   offsets: 2 warp-uniform LDG.128 per quad (1 wf each)
//   gather: lane l loads channels l and l+32 (full 128B lines, 1 wf each)
//   store:  STS.128 of 4 pixels per channel row (4x fewer STS than R9)
// GEMM: thread = 8 pix x 4 oc, f32x2; conflict-free LDS
// ============================================================
__global__ __launch_bounds__(256, 4) void deform_kernel(
    const float* __restrict__ bias,
    float* __restrict__ out)
{
    extern __shared__ float smem[];
    float* sS  = smem;              // 64*132 = 8448 floats
    float* wSh = smem + 64 * PIT;   // 4096 floats

    int tid  = threadIdx.x;
    int warp = tid >> 5;
    int lane = tid & 31;
    int b    = blockIdx.z;
    int wo0  = blockIdx.x * 16;
    int ho0  = blockIdx.y * 8;
    int ho_w = ho0 + warp;          // this warp's output row

    // GEMM mapping: warp = 8 oc-groups (lane&7) x 4 pix-groups (lane>>3)
    int ocg  = (lane & 7) | ((warp & 1) << 3);   // 0..15
    int pixg = (lane >> 3) | ((warp >> 1) << 2); // 0..15
    int oc0  = ocg * 4;
    int p0   = pixg * 8;

    unsigned long long acc[4][4];   // [pixel-pair q][oc j]
#pragma unroll
    for (int i = 0; i < 4; ++i)
#pragma unroll
        for (int j = 0; j < 4; ++j) acc[i][j] = 0ull;

    const float* offb = g_off + (size_t)b * OFFC * HW;
    const float* xTb  = g_xT + (size_t)b * HW * CIN;

    for (int kk = 0; kk < KK; ++kk) {
        if (kk > 0) __syncthreads();   // prev GEMM done reading sS/wSh

        // ---- stage weight chunk wT[kk]: 4096 floats ----
        {
            const float4* src = (const float4*)(g_wT + kk * CIN * COUT);
            float4* dst = (float4*)wSh;
#pragma unroll
            for (int r = 0; r < 4; ++r)
                dst[tid + r * 256] = src[tid + r * 256];
        }

        // ---- sampling: 4 quads of 4 pixels; lane = channels (l, l+32) ----
        {
            int ky = kk / 3 - 1;
            int kx = kk % 3 - 1;
            const float* oyp = offb + (size_t)(2 * kk) * HW + ho_w * W_ + wo0;
#pragma unroll
            for (int t = 0; t < 4; ++t) {
                // warp-uniform offset loads: 4 pixels at once
                float4 offy4 = __ldg((const float4*)(oyp + 4 * t));
                float4 offx4 = __ldg((const float4*)(oyp + HW + 4 * t));

                float aLo[4], aHi[4];
#pragma unroll
                for (int q = 0; q < 4; ++q) {
                    float offy = (q == 0) ? offy4.x : (q == 1) ? offy4.y : (q == 2) ? offy4.z : offy4.w;
                    float offx = (q == 0) ? offx4.x : (q == 1) ? offx4.y : (q == 2) ? offx4.z : offx4.w;
                    int wo_s = wo0 + 4 * t + q;
                    float sy = (float)(ho_w + 1 + ky) + offy;
                    float sx = (float)(wo_s + 1 + kx) + offx;
                    float y0f = floorf(sy), x0f = floorf(sx);
                    float wy1 = sy - y0f, wx1 = sx - x0f;
                    float wy0 = 1.f - wy1, wx0 = 1.f - wx1;
                    int y0 = (int)y0f, x0 = (int)x0f;
                    int y1 = y0 + 1,   x1 = x0 + 1;
                    bool vy0 = ((unsigned)y0 < (unsigned)H_);
                    bool vy1 = ((unsigned)y1 < (unsigned)H_);
                    bool vx0 = ((unsigned)x0 < (unsigned)W_);
                    bool vx1 = ((unsigned)x1 < (unsigned)W_);

                    float aL = 0.f, aH = 0.f;
#define GC(YI, XI, WW, V)                                                   \
                    if (V) {                                                \
                        const float* pb_ = xTb + (size_t)((YI) * W_ + (XI)) * CIN; \
                        float ww = (WW);                                    \
                        aL = fmaf(ww, __ldg(pb_ + lane),      aL);          \
                        aH = fmaf(ww, __ldg(pb_ + lane + 32), aH);          \
                    }
                    GC(y0, x0, wy0 * wx0, vy0 && vx0)
                    GC(y0, x1, wy0 * wx1, vy0 && vx1)
                    GC(y1, x0, wy1 * wx0, vy1 && vx0)
                    GC(y1, x1, wy1 * wx1, vy1 && vx1)
#undef GC
                    aLo[q] = aL; aHi[q] = aH;
                }
                int col = warp * 16 + 4 * t;
                *(float4*)&sS[lane * PIT + col]        = make_float4(aLo[0], aLo[1], aLo[2], aLo[3]);
                *(float4*)&sS[(lane + 32) * PIT + col] = make_float4(aHi[0], aHi[1], aHi[2], aHi[3]);
            }
        }

        __syncthreads();

        // ---- f32x2 GEMM: 8 pix x 4 oc per thread ----
#pragma unroll 4
        for (int c = 0; c < CIN; ++c) {
            ulonglong2 spA = *(const ulonglong2*)&sS[c * PIT + p0];
            ulonglong2 spB = *(const ulonglong2*)&sS[c * PIT + p0 + 4];
            float4 wv = *(const float4*)&wSh[c * 64 + oc0];
            unsigned long long w0 = pack2(wv.x, wv.x);
            unsigned long long w1 = pack2(wv.y, wv.y);
            unsigned long long w2 = pack2(wv.z, wv.z);
            unsigned long long w3 = pack2(wv.w, wv.w);
            acc[0][0] = fma2(spA.x, w0, acc[0][0]);
            acc[0][1] = fma2(spA.x, w1, acc[0][1]);
            acc[0][2] = fma2(spA.x, w2, acc[0][2]);
            acc[0][3] = fma2(spA.x, w3, acc[0][3]);
            acc[1][0] = fma2(spA.y, w0, acc[1][0]);
            acc[1][1] = fma2(spA.y, w1, acc[1][1]);
            acc[1][2] = fma2(spA.y, w2, acc[1][2]);
            acc[1][3] = fma2(spA.y, w3, acc[1][3]);
            acc[2][0] = fma2(spB.x, w0, acc[2][0]);
            acc[2][1] = fma2(spB.x, w1, acc[2][1]);
            acc[2][2] = fma2(spB.x, w2, acc[2][2]);
            acc[2][3] = fma2(spB.x, w3, acc[2][3]);
            acc[3][0] = fma2(spB.y, w0, acc[3][0]);
            acc[3][1] = fma2(spB.y, w1, acc[3][1]);
            acc[3][2] = fma2(spB.y, w2, acc[3][2]);
            acc[3][3] = fma2(spB.y, w3, acc[3][3]);
        }
    }

    // ---- epilogue: write acc to sS as [oc][pix], coalesced NCHW stores ----
    __syncthreads();
#pragma unroll
    for (int q = 0; q < 4; ++q)
#pragma unroll
        for (int j = 0; j < 4; ++j)
            *(unsigned long long*)&sS[(oc0 + j) * PIT + p0 + 2 * q] = acc[q][j];
    __syncthreads();

    float* outb = out + (size_t)b * COUT * HW;
#pragma unroll
    for (int r = 0; r < 32; ++r) {
        int idx = r * 256 + tid;
        int oc  = idx >> 7;
        int pix = idx & 127;
        int ho  = ho0 + (pix >> 4);
        int wo  = wo0 + (pix & 15);
        outb[(size_t)oc * HW + ho * W_ + wo] = sS[oc * PIT + pix] + __ldg(&bias[oc]);
    }
}

// ============================================================
// launch
// ============================================================
extern "C" void kernel_launch(void* const* d_in, const int* in_sizes, int n_in,
                              void* d_out, int out_size)
{
    const float* x      = (const float*)d_in[0];
    const float* weight = (const float*)d_in[1];
    const float* bias   = (const float*)d_in[2];
    const float* off_w  = (const float*)d_in[3];
    const float* off_b  = (const float*)d_in[4];
    float* out = (float*)d_out;

    const int deform_smem = (64 * PIT + 64 * 64) * 4;   // 50176 B
    cudaFuncSetAttribute(deform_kernel,
                         cudaFuncAttributeMaxDynamicSharedMemorySize, deform_smem);

    // 1) layout transforms
    {
        dim3 grid(HW / 32, CIN / 32, B_);
        dim3 block(32, 8);
        transpose_x_kernel<<<grid, block>>>(x);
    }
    {
        int n = COUT * CIN * KK;
        transpose_w_kernel<<<(n + 255) / 256, 256>>>(weight);
    }
    // 2) offset conv
    {
        dim3 grid(W_ / 32, H_ / 8, B_);
        offset_conv_kernel<<<grid, 256>>>(x, off_w, off_b);
    }
    // 3) deformable conv
    {
        dim3 grid(W_ / 16, H_ / 8, B_);
        deform_kernel<<<grid, 256, deform_smem>>>(bias, out);
    }
}

// round 11
// speedup vs baseline: 1.0724x; 1.0724x over previous
#include <cuda_runtime.h>
#include <cstdint>

// ---------------- constants ----------------
#define B_   8
#define CIN  64
#define COUT 64
#define H_   96
#define W_   96
#define HW   (H_*W_)          // 9216
#define KK   9                // 3x3 taps
#define OFFC 18               // 2*KK offset channels
#define PIT  132              // sS pixel pitch (16B-aligned rows)

// ---------------- f32x2 helpers (Blackwell packed fp32) ----------------
__device__ __forceinline__ unsigned long long fma2(unsigned long long a,
                                                   unsigned long long b,
                                                   unsigned long long c) {
    unsigned long long d;
    asm("fma.rn.f32x2 %0, %1, %2, %3;" : "=l"(d) : "l"(a), "l"(b), "l"(c));
    return d;
}
__device__ __forceinline__ unsigned long long pack2(float lo, float hi) {
    unsigned long long d;
    asm("mov.b64 %0, {%1, %2};" : "=l"(d) : "f"(lo), "f"(hi));
    return d;
}
__device__ __forceinline__ float2 unpack2(unsigned long long v) {
    float2 r;
    asm("mov.b64 {%0, %1}, %2;" : "=f"(r.x), "=f"(r.y) : "l"(v));
    return r;
}

// ---------------- scratch ----------------
__device__ float g_xT[B_ * HW * CIN];       // NHWC transposed x
__device__ float g_off[B_ * OFFC * HW];     // offset field
__device__ float g_wT[KK * CIN * COUT];     // weight as [kk][c][oc]

// ============================================================
// Kernel 1: NCHW -> NHWC transpose of x
// ============================================================
__global__ __launch_bounds__(256) void transpose_x_kernel(const float* __restrict__ x)
{
    __shared__ float tile[32][33];
    int b   = blockIdx.z;
    int hw0 = blockIdx.x * 32;
    int c0  = blockIdx.y * 32;
    int tx = threadIdx.x, ty = threadIdx.y;

    const float* src = x + (size_t)b * CIN * HW;
#pragma unroll
    for (int i = 0; i < 32; i += 8)
        tile[ty + i][tx] = src[(size_t)(c0 + ty + i) * HW + hw0 + tx];
    __syncthreads();
    float* dst = g_xT + (size_t)b * HW * CIN;
#pragma unroll
    for (int i = 0; i < 32; i += 8)
        dst[(size_t)(hw0 + ty + i) * CIN + c0 + tx] = tile[tx][ty + i];
}

// ============================================================
// Kernel 2: weight (oc, c, kk) -> wT[kk][c][oc]
// ============================================================
__global__ __launch_bounds__(256) void transpose_w_kernel(const float* __restrict__ w)
{
    int idx = blockIdx.x * 256 + threadIdx.x;
    if (idx < COUT * CIN * KK) {
        int kk = idx % KK;
        int c  = (idx / KK) % CIN;
        int oc = idx / (KK * CIN);
        g_wT[(kk * CIN + c) * COUT + oc] = w[idx];
    }
}

// ============================================================
// Kernel 3: offset conv with f32x2
// ============================================================
__global__ __launch_bounds__(256) void offset_conv_kernel(
    const float* __restrict__ x,
    const float* __restrict__ off_w,
    const float* __restrict__ off_b)
{
    __shared__ float wS[576][20];

    int tid = threadIdx.x;
    for (int i = tid; i < OFFC * 576; i += 256) {
        int o = i / 576;
        int r = i % 576;
        wS[r][o] = off_w[i];
    }
    for (int r = tid; r < 576; r += 256) { wS[r][18] = 0.f; wS[r][19] = 0.f; }
    __syncthreads();

    int b   = blockIdx.z;
    int wo  = blockIdx.x * 32 + (tid & 31);
    int ho  = blockIdx.y * 8  + (tid >> 5);

    unsigned long long acc2[9];
#pragma unroll
    for (int j = 0; j < 9; ++j) acc2[j] = 0ull;

    const float* xb = x + (size_t)b * CIN * HW;

    for (int c = 0; c < CIN; ++c) {
        const float* xc = xb + (size_t)c * HW;
#pragma unroll
        for (int kh = 0; kh < 3; ++kh) {
            int y = ho + kh - 1;
            bool vy = ((unsigned)y < (unsigned)H_);
#pragma unroll
            for (int kw = 0; kw < 3; ++kw) {
                int xx = wo + kw - 1;
                float xv = 0.f;
                if (vy && (unsigned)xx < (unsigned)W_)
                    xv = __ldg(xc + y * W_ + xx);
                unsigned long long xp = pack2(xv, xv);
                const float* wr = &wS[c * 9 + kh * 3 + kw][0];
                ulonglong2 wA = *(const ulonglong2*)(wr + 0);
                ulonglong2 wB = *(const ulonglong2*)(wr + 4);
                ulonglong2 wC = *(const ulonglong2*)(wr + 8);
                ulonglong2 wD = *(const ulonglong2*)(wr + 12);
                unsigned long long wE = *(const unsigned long long*)(wr + 16);
                acc2[0] = fma2(xp, wA.x, acc2[0]);
                acc2[1] = fma2(xp, wA.y, acc2[1]);
                acc2[2] = fma2(xp, wB.x, acc2[2]);
                acc2[3] = fma2(xp, wB.y, acc2[3]);
                acc2[4] = fma2(xp, wC.x, acc2[4]);
                acc2[5] = fma2(xp, wC.y, acc2[5]);
                acc2[6] = fma2(xp, wD.x, acc2[6]);
                acc2[7] = fma2(xp, wD.y, acc2[7]);
                acc2[8] = fma2(xp, wE,   acc2[8]);
            }
        }
    }

#pragma unroll
    for (int j = 0; j < 9; ++j) {
        float2 f = unpack2(acc2[j]);
        g_off[((size_t)(b * OFFC + 2 * j)     * H_ + ho) * W_ + wo] = f.x + __ldg(&off_b[2 * j]);
        g_off[((size_t)(b * OFFC + 2 * j + 1) * H_ + ho) * W_ + wo] = f.y + __ldg(&off_b[2 * j + 1]);
    }
}

// ============================================================
// Kernel 4: deformable conv main — R9 + quad STS.128
// block: 128 pixels (8 ho x 16 wo) x 64 oc, 256 threads, grid (6,12,8)=576
// smem (dynamic 59.4KB): sS[64][PIT] + wSh[64][64] + sOff[18][128]
// sampling: warp w owns pixels 16w..16w+15 as 4 quads; lane = channels (l, l+32)
//   gather: LDG.32 full 128B lines (1 wf each)
//   store:  STS.128 of 4 pixels per channel row — phase-conflict-free (4 wf each)
// GEMM: thread = 8 pix x 4 oc, f32x2
// ============================================================
__global__ __launch_bounds__(256, 3) void deform_kernel(
    const float* __restrict__ bias,
    float* __restrict__ out)
{
    extern __shared__ float smem[];
    float* sS   = smem;                      // 64*132 = 8448
    float* wSh  = smem + 64 * PIT;           // 4096
    float* sOff = smem + 64 * PIT + 64 * 64; // 2304

    int tid  = threadIdx.x;
    int warp = tid >> 5;
    int lane = tid & 31;
    int b    = blockIdx.z;
    int wo0  = blockIdx.x * 16;
    int ho0  = blockIdx.y * 8;
    int ho_w = ho0 + warp;          // warp's output row (pix>>4 == warp)

    // GEMM mapping: warp = 8 oc-groups (lane&7) x 4 pix-groups (lane>>3)
    int ocg  = (lane & 7) | ((warp & 1) << 3);   // 0..15
    int pixg = (lane >> 3) | ((warp >> 1) << 2); // 0..15
    int oc0  = ocg * 4;
    int p0   = pixg * 8;

    // ---- stage offsets (18 x 128) ----
    const float* offb = g_off + (size_t)b * OFFC * HW;
    for (int i = tid; i < OFFC * 128; i += 256) {
        int o = i >> 7;
        int p = i & 127;
        sOff[o * 128 + p] = offb[(size_t)o * HW + (ho0 + (p >> 4)) * W_ + wo0 + (p & 15)];
    }

    unsigned long long acc[4][4];   // [pixel-pair q][oc j]
#pragma unroll
    for (int i = 0; i < 4; ++i)
#pragma unroll
        for (int j = 0; j < 4; ++j) acc[i][j] = 0ull;

    const float* xTb = g_xT + (size_t)b * HW * CIN;

    for (int kk = 0; kk < KK; ++kk) {
        __syncthreads();   // offsets ready (iter 0) / prev GEMM done reading

        // ---- stage weight chunk wT[kk]: 4096 floats ----
        {
            const float4* src = (const float4*)(g_wT + kk * CIN * COUT);
            float4* dst = (float4*)wSh;
#pragma unroll
            for (int r = 0; r < 4; ++r)
                dst[tid + r * 256] = src[tid + r * 256];
        }

        // ---- sampling: 4 quads of 4 pixels; lane = channels (l, l+32) ----
        {
            int ky = kk / 3 - 1;
            int kx = kk % 3 - 1;
#pragma unroll
            for (int t = 0; t < 4; ++t) {
                float aLo[4], aHi[4];
#pragma unroll
                for (int q = 0; q < 4; ++q) {
                    int pix  = warp * 16 + t * 4 + q;
                    int wo_s = wo0 + (t * 4 + q);
                    float offy = sOff[(2 * kk) * 128 + pix];       // broadcast LDS
                    float offx = sOff[(2 * kk + 1) * 128 + pix];   // broadcast LDS
                    float sy = (float)(ho_w + 1 + ky) + offy;
                    float sx = (float)(wo_s + 1 + kx) + offx;
                    float y0f = floorf(sy), x0f = floorf(sx);
                    float wy1 = sy - y0f, wx1 = sx - x0f;
                    float wy0 = 1.f - wy1, wx0 = 1.f - wx1;
                    int y0 = (int)y0f, x0 = (int)x0f;
                    int y1 = y0 + 1,   x1 = x0 + 1;
                    bool vy0 = ((unsigned)y0 < (unsigned)H_);
                    bool vy1 = ((unsigned)y1 < (unsigned)H_);
                    bool vx0 = ((unsigned)x0 < (unsigned)W_);
                    bool vx1 = ((unsigned)x1 < (unsigned)W_);

                    float aL = 0.f, aH = 0.f;
#define GC(YI, XI, WW, V)                                                   \
                    if (V) {                                                \
                        const float* pb_ = xTb + (size_t)((YI) * W_ + (XI)) * CIN; \
                        float ww = (WW);                                    \
                        aL = fmaf(ww, __ldg(pb_ + lane),      aL);          \
                        aH = fmaf(ww, __ldg(pb_ + lane + 32), aH);          \
                    }
                    GC(y0, x0, wy0 * wx0, vy0 && vx0)
                    GC(y0, x1, wy0 * wx1, vy0 && vx1)
                    GC(y1, x0, wy1 * wx0, vy1 && vx0)
                    GC(y1, x1, wy1 * wx1, vy1 && vx1)
#undef GC
                    aLo[q] = aL; aHi[q] = aH;
                }
                int col = warp * 16 + t * 4;
                *(float4*)&sS[lane * PIT + col]        = make_float4(aLo[0], aLo[1], aLo[2], aLo[3]);
                *(float4*)&sS[(lane + 32) * PIT + col] = make_float4(aHi[0], aHi[1], aHi[2], aHi[3]);
            }
        }

        __syncthreads();

        // ---- f32x2 GEMM: 8 pix x 4 oc per thread ----
#pragma unroll 4
        for (int c = 0; c < CIN; ++c) {
            ulonglong2 spA = *(const ulonglong2*)&sS[c * PIT + p0];
            ulonglong2 spB = *(const ulonglong2*)&sS[c * PIT + p0 + 4];
            float4 wv = *(const float4*)&wSh[c * 64 + oc0];
            unsigned long long w0 = pack2(wv.x, wv.x);
            unsigned long long w1 = pack2(wv.y, wv.y);
            unsigned long long w2 = pack2(wv.z, wv.z);
            unsigned long long w3 = pack2(wv.w, wv.w);
            acc[0][0] = fma2(spA.x, w0, acc[0][0]);
            acc[0][1] = fma2(spA.x, w1, acc[0][1]);
            acc[0][2] = fma2(spA.x, w2, acc[0][2]);
            acc[0][3] = fma2(spA.x, w3, acc[0][3]);
            acc[1][0] = fma2(spA.y, w0, acc[1][0]);
            acc[1][1] = fma2(spA.y, w1, acc[1][1]);
            acc[1][2] = fma2(spA.y, w2, acc[1][2]);
            acc[1][3] = fma2(spA.y, w3, acc[1][3]);
            acc[2][0] = fma2(spB.x, w0, acc[2][0]);
            acc[2][1] = fma2(spB.x, w1, acc[2][1]);
            acc[2][2] = fma2(spB.x, w2, acc[2][2]);
            acc[2][3] = fma2(spB.x, w3, acc[2][3]);
            acc[3][0] = fma2(spB.y, w0, acc[3][0]);
            acc[3][1] = fma2(spB.y, w1, acc[3][1]);
            acc[3][2] = fma2(spB.y, w2, acc[3][2]);
            acc[3][3] = fma2(spB.y, w3, acc[3][3]);
        }
    }

    // ---- epilogue: write acc to sS as [oc][pix], coalesced NCHW stores ----
    __syncthreads();
#pragma unroll
    for (int q = 0; q < 4; ++q)
#pragma unroll
        for (int j = 0; j < 4; ++j)
            *(unsigned long long*)&sS[(oc0 + j) * PIT + p0 + 2 * q] = acc[q][j];
    __syncthreads();

    float* outb = out + (size_t)b * COUT * HW;
#pragma unroll
    for (int r = 0; r < 32; ++r) {
        int idx = r * 256 + tid;
        int oc  = idx >> 7;
        int pix = idx & 127;
        int ho  = ho0 + (pix >> 4);
        int wo  = wo0 + (pix & 15);
        outb[(size_t)oc * HW + ho * W_ + wo] = sS[oc * PIT + pix] + __ldg(&bias[oc]);
    }
}

// ============================================================
// launch
// ============================================================
extern "C" void kernel_launch(void* const* d_in, const int* in_sizes, int n_in,
                              void* d_out, int out_size)
{
    const float* x      = (const float*)d_in[0];
    const float* weight = (const float*)d_in[1];
    const float* bias   = (const float*)d_in[2];
    const float* off_w  = (const float*)d_in[3];
    const float* off_b  = (const float*)d_in[4];
    float* out = (float*)d_out;

    const int deform_smem = (64 * PIT + 64 * 64 + OFFC * 128) * 4;   // 59392 B
    cudaFuncSetAttribute(deform_kernel,
                         cudaFuncAttributeMaxDynamicSharedMemorySize, deform_smem);

    // 1) layout transforms
    {
        dim3 grid(HW / 32, CIN / 32, B_);
        dim3 block(32, 8);
        transpose_x_kernel<<<grid, block>>>(x);
    }
    {
        int n = COUT * CIN * KK;
        transpose_w_kernel<<<(n + 255) / 256, 256>>>(weight);
    }
    // 2) offset conv
    {
        dim3 grid(W_ / 32, H_ / 8, B_);
        offset_conv_kernel<<<grid, 256>>>(x, off_w, off_b);
    }
    // 3) deformable conv
    {
        dim3 grid(W_ / 16, H_ / 8, B_);
        deform_kernel<<<grid, 256, deform_smem>>>(bias, out);
    }
}

// round 12
// speedup vs baseline: 1.1918x; 1.1113x over previous
#include <cuda_runtime.h>
#include <cstdint>

// ---------------- constants ----------------
#define B_   8
#define CIN  64
#define COUT 64
#define H_   96
#define W_   96
#define HW   (H_*W_)          // 9216
#define KK   9                // 3x3 taps
#define OFFC 18               // 2*KK offset channels
#define PIT  132              // sS pixel pitch (16B-aligned rows)

// ---------------- f32x2 helpers (Blackwell packed fp32) ----------------
__device__ __forceinline__ unsigned long long fma2(unsigned long long a,
                                                   unsigned long long b,
                                                   unsigned long long c) {
    unsigned long long d;
    asm("fma.rn.f32x2 %0, %1, %2, %3;" : "=l"(d) : "l"(a), "l"(b), "l"(c));
    return d;
}
__device__ __forceinline__ unsigned long long pack2(float lo, float hi) {
    unsigned long long d;
    asm("mov.b64 %0, {%1, %2};" : "=l"(d) : "f"(lo), "f"(hi));
    return d;
}
__device__ __forceinline__ float2 unpack2(unsigned long long v) {
    float2 r;
    asm("mov.b64 {%0, %1}, %2;" : "=f"(r.x), "=f"(r.y) : "l"(v));
    return r;
}

// ---------------- scratch ----------------
__device__ float g_xT[B_ * HW * CIN];       // NHWC transposed x
__device__ float g_off[B_ * OFFC * HW];     // offset field
__device__ float g_wT[KK * CIN * COUT];     // weight as [kk][c][oc]

// ============================================================
// Kernel 1: NCHW -> NHWC transpose of x
// ============================================================
__global__ __launch_bounds__(256) void transpose_x_kernel(const float* __restrict__ x)
{
    __shared__ float tile[32][33];
    int b   = blockIdx.z;
    int hw0 = blockIdx.x * 32;
    int c0  = blockIdx.y * 32;
    int tx = threadIdx.x, ty = threadIdx.y;

    const float* src = x + (size_t)b * CIN * HW;
#pragma unroll
    for (int i = 0; i < 32; i += 8)
        tile[ty + i][tx] = src[(size_t)(c0 + ty + i) * HW + hw0 + tx];
    __syncthreads();
    float* dst = g_xT + (size_t)b * HW * CIN;
#pragma unroll
    for (int i = 0; i < 32; i += 8)
        dst[(size_t)(hw0 + ty + i) * CIN + c0 + tx] = tile[tx][ty + i];
}

// ============================================================
// Kernel 2: weight (oc, c, kk) -> wT[kk][c][oc]
// ============================================================
__global__ __launch_bounds__(256) void transpose_w_kernel(const float* __restrict__ w)
{
    int idx = blockIdx.x * 256 + threadIdx.x;
    if (idx < COUT * CIN * KK) {
        int kk = idx % KK;
        int c  = (idx / KK) % CIN;
        int oc = idx / (KK * CIN);
        g_wT[(kk * CIN + c) * COUT + oc] = w[idx];
    }
}

// ============================================================
// Kernel 3: offset conv with f32x2
// ============================================================
__global__ __launch_bounds__(256) void offset_conv_kernel(
    const float* __restrict__ x,
    const float* __restrict__ off_w,
    const float* __restrict__ off_b)
{
    __shared__ float wS[576][20];

    int tid = threadIdx.x;
    for (int i = tid; i < OFFC * 576; i += 256) {
        int o = i / 576;
        int r = i % 576;
        wS[r][o] = off_w[i];
    }
    for (int r = tid; r < 576; r += 256) { wS[r][18] = 0.f; wS[r][19] = 0.f; }
    __syncthreads();

    int b   = blockIdx.z;
    int wo  = blockIdx.x * 32 + (tid & 31);
    int ho  = blockIdx.y * 8  + (tid >> 5);

    unsigned long long acc2[9];
#pragma unroll
    for (int j = 0; j < 9; ++j) acc2[j] = 0ull;

    const float* xb = x + (size_t)b * CIN * HW;

    for (int c = 0; c < CIN; ++c) {
        const float* xc = xb + (size_t)c * HW;
#pragma unroll
        for (int kh = 0; kh < 3; ++kh) {
            int y = ho + kh - 1;
            bool vy = ((unsigned)y < (unsigned)H_);
#pragma unroll
            for (int kw = 0; kw < 3; ++kw) {
                int xx = wo + kw - 1;
                float xv = 0.f;
                if (vy && (unsigned)xx < (unsigned)W_)
                    xv = __ldg(xc + y * W_ + xx);
                unsigned long long xp = pack2(xv, xv);
                const float* wr = &wS[c * 9 + kh * 3 + kw][0];
                ulonglong2 wA = *(const ulonglong2*)(wr + 0);
                ulonglong2 wB = *(const ulonglong2*)(wr + 4);
                ulonglong2 wC = *(const ulonglong2*)(wr + 8);
                ulonglong2 wD = *(const ulonglong2*)(wr + 12);
                unsigned long long wE = *(const unsigned long long*)(wr + 16);
                acc2[0] = fma2(xp, wA.x, acc2[0]);
                acc2[1] = fma2(xp, wA.y, acc2[1]);
                acc2[2] = fma2(xp, wB.x, acc2[2]);
                acc2[3] = fma2(xp, wB.y, acc2[3]);
                acc2[4] = fma2(xp, wC.x, acc2[4]);
                acc2[5] = fma2(xp, wC.y, acc2[5]);
                acc2[6] = fma2(xp, wD.x, acc2[6]);
                acc2[7] = fma2(xp, wD.y, acc2[7]);
                acc2[8] = fma2(xp, wE,   acc2[8]);
            }
        }
    }

#pragma unroll
    for (int j = 0; j < 9; ++j) {
        float2 f = unpack2(acc2[j]);
        g_off[((size_t)(b * OFFC + 2 * j)     * H_ + ho) * W_ + wo] = f.x + __ldg(&off_b[2 * j]);
        g_off[((size_t)(b * OFFC + 2 * j + 1) * H_ + ho) * W_ + wo] = f.y + __ldg(&off_b[2 * j + 1]);
    }
}

// ============================================================
// Kernel 4: deformable conv main — precomputed bilinear params
// block: 128 pixels (8 ho x 16 wo) x 64 oc, 256 threads, grid (6,12,8)=576
// smem 54.3KB: sS[64][PIT] + wSh[64][64] + sParO[128][4] + sParW[128][4]
// per tap: threads 0-127 compute per-pixel params (clamped byte offsets +
//          validity-folded weights); threads 128-255 stage the weight chunk.
// gather: branch-free, per pixel 2 broadcast LDS.128 + 4x(2 LDG + 2 FFMA)
// GEMM: thread = 8 pix x 4 oc, f32x2 (R11 shape)
// ============================================================
__global__ __launch_bounds__(256, 3) void deform_kernel(
    const float* __restrict__ bias,
    float* __restrict__ out)
{
    extern __shared__ float smem[];
    float* sS    = smem;                             // 8448
    float* wSh   = smem + 64 * PIT;                  // 4096
    int*   sParO = (int*)(smem + 64 * PIT + 4096);   // 512 ints
    float* sParW = smem + 64 * PIT + 4096 + 512;     // 512 floats

    int tid  = threadIdx.x;
    int warp = tid >> 5;
    int lane = tid & 31;
    int b    = blockIdx.z;
    int wo0  = blockIdx.x * 16;
    int ho0  = blockIdx.y * 8;

    // GEMM mapping: warp = 8 oc-groups (lane&7) x 4 pix-groups (lane>>3)
    int ocg  = (lane & 7) | ((warp & 1) << 3);   // 0..15
    int pixg = (lane >> 3) | ((warp >> 1) << 2); // 0..15
    int oc0  = ocg * 4;
    int p0   = pixg * 8;

    unsigned long long acc[4][4];   // [pixel-pair q][oc j]
#pragma unroll
    for (int i = 0; i < 4; ++i)
#pragma unroll
        for (int j = 0; j < 4; ++j) acc[i][j] = 0ull;

    const float* offb = g_off + (size_t)b * OFFC * HW;
    const float* xTb  = g_xT + (size_t)b * HW * CIN;
    const char*  xL   = (const char*)(xTb + lane);
    const char*  xH   = (const char*)(xTb + lane + 32);

    for (int kk = 0; kk < KK; ++kk) {
        if (kk > 0) __syncthreads();   // prev GEMM done reading sS/wSh

        if (tid < 128) {
            // ---- per-pixel bilinear setup (1 thread = 1 pixel) ----
            int pix  = tid;
            int ho_s = ho0 + (pix >> 4);
            int wo_s = wo0 + (pix & 15);
            int ky = kk / 3 - 1;
            int kx = kk % 3 - 1;
            float offy = __ldg(offb + (size_t)(2 * kk) * HW + ho_s * W_ + wo_s);
            float offx = __ldg(offb + (size_t)(2 * kk + 1) * HW + ho_s * W_ + wo_s);
            float sy = (float)(ho_s + 1 + ky) + offy;
            float sx = (float)(wo_s + 1 + kx) + offx;
            float y0f = floorf(sy), x0f = floorf(sx);
            float wy1 = sy - y0f, wx1 = sx - x0f;
            float wy0 = 1.f - wy1, wx0 = 1.f - wx1;
            int y0 = (int)y0f, x0 = (int)x0f;
            int y1 = y0 + 1,   x1 = x0 + 1;
            float fy0 = ((unsigned)y0 < (unsigned)H_) ? 1.f : 0.f;
            float fy1 = ((unsigned)y1 < (unsigned)H_) ? 1.f : 0.f;
            float fx0 = ((unsigned)x0 < (unsigned)W_) ? 1.f : 0.f;
            float fx1 = ((unsigned)x1 < (unsigned)W_) ? 1.f : 0.f;
            int y0c = min(max(y0, 0), H_ - 1);
            int y1c = min(max(y1, 0), H_ - 1);
            int x0c = min(max(x0, 0), W_ - 1);
            int x1c = min(max(x1, 0), W_ - 1);
            // byte offsets into NHWC x (CIN*4 = 256 B per pixel)
            int o00 = (y0c * W_ + x0c) * (CIN * 4);
            int o01 = (y0c * W_ + x1c) * (CIN * 4);
            int o10 = (y1c * W_ + x0c) * (CIN * 4);
            int o11 = (y1c * W_ + x1c) * (CIN * 4);
            *(int4*)&sParO[pix * 4] = make_int4(o00, o01, o10, o11);
            *(float4*)&sParW[pix * 4] = make_float4(wy0 * wx0 * fy0 * fx0,
                                                    wy0 * wx1 * fy0 * fx1,
                                                    wy1 * wx0 * fy1 * fx0,
                                                    wy1 * wx1 * fy1 * fx1);
        } else {
            // ---- stage weight chunk wT[kk]: 4096 floats by threads 128-255 ----
            int t2 = tid - 128;
            const float4* src = (const float4*)(g_wT + kk * CIN * COUT);
            float4* dst = (float4*)wSh;
#pragma unroll
            for (int r = 0; r < 8; ++r)
                dst[t2 + r * 128] = src[t2 + r * 128];
        }

        __syncthreads();   // params + weights ready

        // ---- branch-free gather: warp owns 16 pixels as 4 quads ----
#pragma unroll
        for (int t = 0; t < 4; ++t) {
            float aLo[4], aHi[4];
#pragma unroll
            for (int q = 0; q < 4; ++q) {
                int pix = warp * 16 + t * 4 + q;
                int4   offs = *(const int4*)&sParO[pix * 4];
                float4 ws   = *(const float4*)&sParW[pix * 4];
                float aL, aH;
                aL = ws.x * __ldg((const float*)(xL + offs.x));
                aH = ws.x * __ldg((const float*)(xH + offs.x));
                aL = fmaf(ws.y, __ldg((const float*)(xL + offs.y)), aL);
                aH = fmaf(ws.y, __ldg((const float*)(xH + offs.y)), aH);
                aL = fmaf(ws.z, __ldg((const float*)(xL + offs.z)), aL);
                aH = fmaf(ws.z, __ldg((const float*)(xH + offs.z)), aH);
                aL = fmaf(ws.w, __ldg((const float*)(xL + offs.w)), aL);
                aH = fmaf(ws.w, __ldg((const float*)(xH + offs.w)), aH);
                aLo[q] = aL; aHi[q] = aH;
            }
            int col = warp * 16 + t * 4;
            *(float4*)&sS[lane * PIT + col]        = make_float4(aLo[0], aLo[1], aLo[2], aLo[3]);
            *(float4*)&sS[(lane + 32) * PIT + col] = make_float4(aHi[0], aHi[1], aHi[2], aHi[3]);
        }

        __syncthreads();

        // ---- f32x2 GEMM: 8 pix x 4 oc per thread ----
#pragma unroll 4
        for (int c = 0; c < CIN; ++c) {
            ulonglong2 spA = *(const ulonglong2*)&sS[c * PIT + p0];
            ulonglong2 spB = *(const ulonglong2*)&sS[c * PIT + p0 + 4];
            float4 wv = *(const float4*)&wSh[c * 64 + oc0];
            unsigned long long w0 = pack2(wv.x, wv.x);
            unsigned long long w1 = pack2(wv.y, wv.y);
            unsigned long long w2 = pack2(wv.z, wv.z);
            unsigned long long w3 = pack2(wv.w, wv.w);
            acc[0][0] = fma2(spA.x, w0, acc[0][0]);
            acc[0][1] = fma2(spA.x, w1, acc[0][1]);
            acc[0][2] = fma2(spA.x, w2, acc[0][2]);
            acc[0][3] = fma2(spA.x, w3, acc[0][3]);
            acc[1][0] = fma2(spA.y, w0, acc[1][0]);
            acc[1][1] = fma2(spA.y, w1, acc[1][1]);
            acc[1][2] = fma2(spA.y, w2, acc[1][2]);
            acc[1][3] = fma2(spA.y, w3, acc[1][3]);
            acc[2][0] = fma2(spB.x, w0, acc[2][0]);
            acc[2][1] = fma2(spB.x, w1, acc[2][1]);
            acc[2][2] = fma2(spB.x, w2, acc[2][2]);
            acc[2][3] = fma2(spB.x, w3, acc[2][3]);
            acc[3][0] = fma2(spB.y, w0, acc[3][0]);
            acc[3][1] = fma2(spB.y, w1, acc[3][1]);
            acc[3][2] = fma2(spB.y, w2, acc[3][2]);
            acc[3][3] = fma2(spB.y, w3, acc[3][3]);
        }
    }

    // ---- epilogue: write acc to sS as [oc][pix], coalesced NCHW stores ----
    __syncthreads();
#pragma unroll
    for (int q = 0; q < 4; ++q)
#pragma unroll
        for (int j = 0; j < 4; ++j)
            *(unsigned long long*)&sS[(oc0 + j) * PIT + p0 + 2 * q] = acc[q][j];
    __syncthreads();

    float* outb = out + (size_t)b * COUT * HW;
#pragma unroll
    for (int r = 0; r < 32; ++r) {
        int idx = r * 256 + tid;
        int oc  = idx >> 7;
        int pix = idx & 127;
        int ho  = ho0 + (pix >> 4);
        int wo  = wo0 + (pix & 15);
        outb[(size_t)oc * HW + ho * W_ + wo] = sS[oc * PIT + pix] + __ldg(&bias[oc]);
    }
}

// ============================================================
// launch
// ============================================================
extern "C" void kernel_launch(void* const* d_in, const int* in_sizes, int n_in,
                              void* d_out, int out_size)
{
    const float* x      = (const float*)d_in[0];
    const float* weight = (const float*)d_in[1];
    const float* bias   = (const float*)d_in[2];
    const float* off_w  = (const float*)d_in[3];
    const float* off_b  = (const float*)d_in[4];
    float* out = (float*)d_out;

    const int deform_smem = (64 * PIT + 4096 + 512 + 512) * 4;   // 54272 B
    cudaFuncSetAttribute(deform_kernel,
                         cudaFuncAttributeMaxDynamicSharedMemorySize, deform_smem);

    // 1) layout transforms
    {
        dim3 grid(HW / 32, CIN / 32, B_);
        dim3 block(32, 8);
        transpose_x_kernel<<<grid, block>>>(x);
    }
    {
        int n = COUT * CIN * KK;
        transpose_w_kernel<<<(n + 255) / 256, 256>>>(weight);
    }
    // 2) offset conv
    {
        dim3 grid(W_ / 32, H_ / 8, B_);
        offset_conv_kernel<<<grid, 256>>>(x, off_w, off_b);
    }
    // 3) deformable conv
    {
        dim3 grid(W_ / 16, H_ / 8, B_);
        deform_kernel<<<grid, 256, deform_smem>>>(bias, out);
    }
}